// round 1
// baseline (speedup 1.0000x reference)
#include <cuda_runtime.h>
#include <cuda_bf16.h>
#include <cstdint>
#include <math.h>

#define MAXB 4096
#define D 512

__device__ __nv_bfloat16 g_V[MAXB * D];   // normalized vision, bf16
__device__ __nv_bfloat16 g_T[MAXB * D];   // normalized text, bf16
__device__ float g_mpr[MAXB];             // mean_pos per vision anchor (row)
__device__ float g_mpc[MAXB];             // mean_pos per text anchor (col)
__device__ float g_negr[MAXB];            // neg_term per row (v2t)
__device__ float g_negc[MAXB];            // neg_term per col (t2v)
__device__ int   g_cnt[MAXB];             // group size (pos_cnt)
__device__ float g_acc[4];                // v2t, t2v, num_pos
__device__ int   g_is64;                  // match_ids layout flag

__device__ __forceinline__ long long load_id(const void* ids, int i) {
    return g_is64 ? ((const long long*)ids)[i] : (long long)((const int*)ids)[i];
}

// ---------------------------------------------------------------------------
// K0: detect int64 vs int32 layout of match_ids.
// Reads only the first B 32-bit words (safe for both layouts). If the data is
// int64 (values < 2048), every odd 32-bit word is 0. If int32, odd words are
// ids themselves (nonzero with overwhelming probability over 2048 samples).
// ---------------------------------------------------------------------------
__global__ void k_detect(const unsigned int* idw, int B) {
    int lane = threadIdx.x;
    bool nz = false;
    for (int idx = 1 + 2 * lane; idx < B; idx += 64) nz |= (idw[idx] != 0u);
    nz = __any_sync(0xffffffffu, nz);
    if (lane == 0) g_is64 = nz ? 0 : 1;
}

// K0b: zero accumulators (must happen every launch — graph replays).
__global__ void k_init(int B) {
    int i = blockIdx.x * blockDim.x + threadIdx.x;
    if (i < B) { g_negr[i] = 0.f; g_negc[i] = 0.f; }
    if (i < 4) g_acc[i] = 0.f;
}

// ---------------------------------------------------------------------------
// K1: L2-normalize rows, write bf16. blockIdx.y selects V (0) or T (1).
// ---------------------------------------------------------------------------
__global__ void k_norm(const float* __restrict__ V, const float* __restrict__ T, int B) {
    int row = blockIdx.x;
    const float* src = blockIdx.y ? T : V;
    __nv_bfloat16* dst = blockIdx.y ? g_T : g_V;
    int tid = threadIdx.x;  // 128 threads
    float x[4];
    float p = 0.f;
#pragma unroll
    for (int u = 0; u < 4; u++) {
        x[u] = src[row * D + tid + u * 128];
        p += x[u] * x[u];
    }
#pragma unroll
    for (int o = 16; o; o >>= 1) p += __shfl_xor_sync(0xffffffffu, p, o);
    __shared__ float s[4];
    if ((tid & 31) == 0) s[tid >> 5] = p;
    __syncthreads();
    float ss = s[0] + s[1] + s[2] + s[3];
    float inv = 1.f / fmaxf(sqrtf(ss), 1e-12f);
#pragma unroll
    for (int u = 0; u < 4; u++)
        dst[row * D + tid + u * 128] = __float2bfloat16(x[u] * inv);
}

// ---------------------------------------------------------------------------
// K2: sparse mean_pos. One warp per anchor. role 0: vision anchor (rows of
// sim) -> g_mpr; role 1: text anchor (cols of sim) -> g_mpc.
// Groups are tiny (~2 members), so scanning all B ids with a warp is cheap.
// ---------------------------------------------------------------------------
__global__ void k_meanpos(const void* __restrict__ ids, int B) {
    int warp = threadIdx.x >> 5;
    int lane = threadIdx.x & 31;
    int a = blockIdx.x * 8 + warp;
    int role = blockIdx.y;
    if (a >= B) return;
    long long ida = load_id(ids, a);
    float sum = 0.f;
    int cnt = 0;
    for (int j0 = 0; j0 < B; j0 += 32) {
        int j = j0 + lane;
        bool m = (load_id(ids, j) == ida);
        unsigned mask = __ballot_sync(0xffffffffu, m);
        while (mask) {
            int jj = j0 + (__ffs(mask) - 1);
            mask &= mask - 1;
            int xi = role ? jj : a;  // vision index
            int yi = role ? a : jj;  // text index
            float d = 0.f;
#pragma unroll
            for (int kk = 0; kk < D / 32; kk++) {
                int k = lane + kk * 32;
                d += __bfloat162float(g_V[xi * D + k]) * __bfloat162float(g_T[yi * D + k]);
            }
#pragma unroll
            for (int o = 16; o; o >>= 1) d += __shfl_xor_sync(0xffffffffu, d, o);
            sum += d;
            cnt++;
        }
    }
    if (lane == 0) {
        float mp = sum / (float)max(cnt, 1);
        if (role == 0) { g_mpr[a] = mp; g_cnt[a] = cnt; }
        else           { g_mpc[a] = mp; }
    }
}

// ---------------------------------------------------------------------------
// K3: fused GEMM + hard-negative epilogue.
// 128x128 block tile, 8 warps (4x2), warp tile 32x64, mma.sync m16n8k16 bf16
// with f32 accumulation. Fragments loaded directly from global (8 MB total,
// L2-resident). Epilogue computes w*exp(sim/T) for non-matches and reduces
// into g_negr / g_negc via shared then global atomics. sim is never stored.
// ---------------------------------------------------------------------------
__global__ __launch_bounds__(256) void k_gemm(const void* __restrict__ ids, int B) {
    __shared__ long long s_idr[128], s_idc[128];
    __shared__ float s_mpr[128], s_mpc[128], s_negr[128], s_negc[128];
    const float TEMP_INV = 14.285714285714286f;
    const float MARGIN = 0.2f;

    int tid = threadIdx.x;
    int row0 = blockIdx.y * 128, col0 = blockIdx.x * 128;
    if (tid < 128) {
        s_idr[tid] = load_id(ids, row0 + tid);
        s_idc[tid] = load_id(ids, col0 + tid);
        s_mpr[tid] = g_mpr[row0 + tid];
        s_mpc[tid] = g_mpc[col0 + tid];
        s_negr[tid] = 0.f;
        s_negc[tid] = 0.f;
    }
    __syncthreads();

    int warp = tid >> 5, lane = tid & 31;
    int wr = warp >> 1, wc = warp & 1;
    int g = lane >> 2, t = lane & 3;
    int rbase = row0 + wr * 32;
    int cbase = col0 + wc * 64;
    const uint32_t* Vw = (const uint32_t*)g_V;  // 2 bf16 per u32, D/2=256 u32/row
    const uint32_t* Tw = (const uint32_t*)g_T;

    float acc[2][8][4];
#pragma unroll
    for (int mt = 0; mt < 2; mt++)
#pragma unroll
        for (int nt = 0; nt < 8; nt++)
#pragma unroll
            for (int v = 0; v < 4; v++) acc[mt][nt][v] = 0.f;

    for (int k0 = 0; k0 < D; k0 += 16) {
        int kw = k0 >> 1;
        uint32_t a[2][4];
#pragma unroll
        for (int mt = 0; mt < 2; mt++) {
            int r = rbase + mt * 16 + g;
            const uint32_t* p = Vw + r * (D / 2) + kw + t;
            a[mt][0] = p[0];                 // (row g,   k=t*2)
            a[mt][1] = p[8 * (D / 2)];       // (row g+8, k=t*2)
            a[mt][2] = p[4];                 // (row g,   k=t*2+8)
            a[mt][3] = p[8 * (D / 2) + 4];   // (row g+8, k=t*2+8)
        }
#pragma unroll
        for (int nt = 0; nt < 8; nt++) {
            int c = cbase + nt * 8 + g;
            const uint32_t* p = Tw + c * (D / 2) + kw + t;
            uint32_t b0 = p[0];              // (k=t*2,   col g)
            uint32_t b1 = p[4];              // (k=t*2+8, col g)
#pragma unroll
            for (int mt = 0; mt < 2; mt++) {
                asm volatile(
                    "mma.sync.aligned.m16n8k16.row.col.f32.bf16.bf16.f32 "
                    "{%0,%1,%2,%3}, {%4,%5,%6,%7}, {%8,%9}, {%0,%1,%2,%3};\n"
                    : "+f"(acc[mt][nt][0]), "+f"(acc[mt][nt][1]),
                      "+f"(acc[mt][nt][2]), "+f"(acc[mt][nt][3])
                    : "r"(a[mt][0]), "r"(a[mt][1]), "r"(a[mt][2]), "r"(a[mt][3]),
                      "r"(b0), "r"(b1));
            }
        }
    }

    // Epilogue: per-thread partials for 4 distinct rows and 16 distinct cols.
    float rloc[4] = {0.f, 0.f, 0.f, 0.f};
    float cloc[16];
#pragma unroll
    for (int q = 0; q < 16; q++) cloc[q] = 0.f;

#pragma unroll
    for (int mt = 0; mt < 2; mt++) {
#pragma unroll
        for (int nt = 0; nt < 8; nt++) {
#pragma unroll
            for (int v = 0; v < 4; v++) {
                float s = acc[mt][nt][v];
                int h = v >> 1, bb = v & 1;
                int rl = wr * 32 + mt * 16 + g + h * 8;   // block-local row
                int cl = wc * 64 + nt * 8 + t * 2 + bb;   // block-local col
                if (s_idr[rl] != s_idc[cl]) {
                    float e = __expf(s * TEMP_INV);
                    float mr = s_mpr[rl];
                    rloc[mt * 2 + h] += (s < mr && s > mr - MARGIN) ? 2.f * e : e;
                    float mc = s_mpc[cl];
                    cloc[nt * 2 + bb] += (s < mc && s > mc - MARGIN) ? 2.f * e : e;
                }
            }
        }
    }

#pragma unroll
    for (int mt = 0; mt < 2; mt++)
#pragma unroll
        for (int h = 0; h < 2; h++)
            atomicAdd(&s_negr[wr * 32 + mt * 16 + g + 8 * h], rloc[mt * 2 + h]);
#pragma unroll
    for (int nt = 0; nt < 8; nt++)
#pragma unroll
        for (int bb = 0; bb < 2; bb++)
            atomicAdd(&s_negc[wc * 64 + nt * 8 + t * 2 + bb], cloc[nt * 2 + bb]);
    __syncthreads();
    if (tid < 128) {
        atomicAdd(&g_negr[row0 + tid], s_negr[tid]);
        atomicAdd(&g_negc[col0 + tid], s_negc[tid]);
    }
}

// ---------------------------------------------------------------------------
// K4: finalize — positive-pair terms. One warp per row i; for each match j:
//   v2t += log1p(neg_row[i]/exp(sim/T)),  t2v += log1p(neg_col[j]/exp(sim/T))
// plus num_pos accumulation.
// ---------------------------------------------------------------------------
__global__ void k_final(const void* __restrict__ ids, int B) {
    const float TEMP_INV = 14.285714285714286f;
    int warp = threadIdx.x >> 5;
    int lane = threadIdx.x & 31;
    int i = blockIdx.x * 8 + warp;
    if (i >= B) return;
    long long idi = load_id(ids, i);
    int cnti = g_cnt[i];
    bool valid_i = (cnti > 0) && (cnti < B);
    float negi = g_negr[i];
    float v2t = 0.f, t2v = 0.f;
    for (int j0 = 0; j0 < B; j0 += 32) {
        int j = j0 + lane;
        bool m = (load_id(ids, j) == idi);
        unsigned mask = __ballot_sync(0xffffffffu, m);
        while (mask) {
            int jj = j0 + (__ffs(mask) - 1);
            mask &= mask - 1;
            float d = 0.f;
#pragma unroll
            for (int kk = 0; kk < D / 32; kk++) {
                int k = lane + kk * 32;
                d += __bfloat162float(g_V[i * D + k]) * __bfloat162float(g_T[jj * D + k]);
            }
#pragma unroll
            for (int o = 16; o; o >>= 1) d += __shfl_xor_sync(0xffffffffu, d, o);
            if (lane == 0) {
                float e = __expf(d * TEMP_INV);
                if (valid_i) v2t += log1pf(negi / e);
                int cntj = g_cnt[jj];
                if (cntj > 0 && cntj < B) t2v += log1pf(g_negc[jj] / e);
            }
        }
    }
    if (lane == 0) {
        atomicAdd(&g_acc[0], v2t);
        atomicAdd(&g_acc[1], t2v);
        atomicAdd(&g_acc[2], (float)cnti);
    }
}

__global__ void k_write(float* out) {
    float np = g_acc[2];
    out[0] = (np > 0.f) ? (g_acc[0] + g_acc[1]) / (2.f * fmaxf(np, 1.f)) : 0.f;
}

// ---------------------------------------------------------------------------
extern "C" void kernel_launch(void* const* d_in, const int* in_sizes, int n_in,
                              void* d_out, int out_size) {
    const float* V = (const float*)d_in[0];
    const float* T = (const float*)d_in[1];
    const void* ids = d_in[2];
    int B = in_sizes[2];
    if (B > MAXB) B = MAXB;

    k_detect<<<1, 32>>>((const unsigned int*)ids, B);
    k_init<<<(B + 255) / 256, 256>>>(B);
    dim3 gn(B, 2);
    k_norm<<<gn, 128>>>(V, T, B);
    dim3 gm((B + 7) / 8, 2);
    k_meanpos<<<gm, 256>>>(ids, B);
    dim3 gg(B / 128, B / 128);
    k_gemm<<<gg, 256>>>(ids, B);
    k_final<<<(B + 7) / 8, 256>>>(ids, B);
    k_write<<<1, 1>>>((float*)d_out);
}

// round 2
// speedup vs baseline: 1.0092x; 1.0092x over previous
#include <cuda_runtime.h>
#include <cuda_bf16.h>
#include <cstdint>
#include <math.h>

#define MAXB 4096
#define D 512

__device__ __nv_bfloat16 g_V[MAXB * D];   // normalized vision, bf16
__device__ __nv_bfloat16 g_T[MAXB * D];   // normalized text, bf16
__device__ float g_mpr[MAXB];             // mean_pos per vision anchor (row)
__device__ float g_mpc[MAXB];             // mean_pos per text anchor (col)
__device__ float g_negr[MAXB];            // neg_term per row (v2t)
__device__ float g_negc[MAXB];            // neg_term per col (t2v)
__device__ int   g_cnt[MAXB];             // group size (pos_cnt)
__device__ float g_acc[4];                // v2t, t2v, num_pos
__device__ int   g_is64;                  // match_ids layout flag

__device__ __forceinline__ long long load_id(const void* ids, int i) {
    return g_is64 ? ((const long long*)ids)[i] : (long long)((const int*)ids)[i];
}

// ---------------------------------------------------------------------------
// K0: detect int64 vs int32 layout of match_ids.
// Reads only the first B 32-bit words (safe for both layouts). If the data is
// int64 (values < 2048), every odd 32-bit word is 0. If int32, odd words are
// ids themselves (nonzero with overwhelming probability over 2048 samples).
// ---------------------------------------------------------------------------
__global__ void k_detect(const unsigned int* idw, int B) {
    int lane = threadIdx.x;
    bool nz = false;
    for (int idx = 1 + 2 * lane; idx < B; idx += 64) nz |= (idw[idx] != 0u);
    nz = __any_sync(0xffffffffu, nz);
    if (lane == 0) g_is64 = nz ? 0 : 1;
}

// K0b: zero accumulators (must happen every launch — graph replays).
__global__ void k_init(int B) {
    int i = blockIdx.x * blockDim.x + threadIdx.x;
    if (i < B) { g_negr[i] = 0.f; g_negc[i] = 0.f; }
    if (i < 4) g_acc[i] = 0.f;
}

// ---------------------------------------------------------------------------
// K1: L2-normalize rows, write bf16. blockIdx.y selects V (0) or T (1).
// ---------------------------------------------------------------------------
__global__ void k_norm(const float* __restrict__ V, const float* __restrict__ T, int B) {
    int row = blockIdx.x;
    const float* src = blockIdx.y ? T : V;
    __nv_bfloat16* dst = blockIdx.y ? g_T : g_V;
    int tid = threadIdx.x;  // 128 threads
    float x[4];
    float p = 0.f;
#pragma unroll
    for (int u = 0; u < 4; u++) {
        x[u] = src[row * D + tid + u * 128];
        p += x[u] * x[u];
    }
#pragma unroll
    for (int o = 16; o; o >>= 1) p += __shfl_xor_sync(0xffffffffu, p, o);
    __shared__ float s[4];
    if ((tid & 31) == 0) s[tid >> 5] = p;
    __syncthreads();
    float ss = s[0] + s[1] + s[2] + s[3];
    float inv = 1.f / fmaxf(sqrtf(ss), 1e-12f);
#pragma unroll
    for (int u = 0; u < 4; u++)
        dst[row * D + tid + u * 128] = __float2bfloat16(x[u] * inv);
}

// ---------------------------------------------------------------------------
// K2: sparse mean_pos. One warp per anchor. role 0: vision anchor (rows of
// sim) -> g_mpr; role 1: text anchor (cols of sim) -> g_mpc.
// Groups are tiny (~2 members), so scanning all B ids with a warp is cheap.
// ---------------------------------------------------------------------------
__global__ void k_meanpos(const void* __restrict__ ids, int B) {
    int warp = threadIdx.x >> 5;
    int lane = threadIdx.x & 31;
    int a = blockIdx.x * 8 + warp;
    int role = blockIdx.y;
    if (a >= B) return;
    long long ida = load_id(ids, a);
    float sum = 0.f;
    int cnt = 0;
    for (int j0 = 0; j0 < B; j0 += 32) {
        int j = j0 + lane;
        bool m = (load_id(ids, j) == ida);
        unsigned mask = __ballot_sync(0xffffffffu, m);
        while (mask) {
            int jj = j0 + (__ffs(mask) - 1);
            mask &= mask - 1;
            int xi = role ? jj : a;  // vision index
            int yi = role ? a : jj;  // text index
            float d = 0.f;
#pragma unroll
            for (int kk = 0; kk < D / 32; kk++) {
                int k = lane + kk * 32;
                d += __bfloat162float(g_V[xi * D + k]) * __bfloat162float(g_T[yi * D + k]);
            }
#pragma unroll
            for (int o = 16; o; o >>= 1) d += __shfl_xor_sync(0xffffffffu, d, o);
            sum += d;
            cnt++;
        }
    }
    if (lane == 0) {
        float mp = sum / (float)max(cnt, 1);
        if (role == 0) { g_mpr[a] = mp; g_cnt[a] = cnt; }
        else           { g_mpc[a] = mp; }
    }
}

// ---------------------------------------------------------------------------
// K3: fused GEMM + hard-negative epilogue.
// 128x128 block tile, 8 warps (4x2), warp tile 32x64, mma.sync m16n8k16 bf16
// with f32 accumulation. Fragments loaded directly from global (8 MB total,
// L2-resident). Epilogue computes w*exp(sim/T) for non-matches and reduces
// into g_negr / g_negc via shared then global atomics. sim is never stored.
// ---------------------------------------------------------------------------
__global__ __launch_bounds__(256) void k_gemm(const void* __restrict__ ids, int B) {
    __shared__ long long s_idr[128], s_idc[128];
    __shared__ float s_mpr[128], s_mpc[128], s_negr[128], s_negc[128];
    const float TEMP_INV = 14.285714285714286f;
    const float MARGIN = 0.2f;

    int tid = threadIdx.x;
    int row0 = blockIdx.y * 128, col0 = blockIdx.x * 128;
    if (tid < 128) {
        s_idr[tid] = load_id(ids, row0 + tid);
        s_idc[tid] = load_id(ids, col0 + tid);
        s_mpr[tid] = g_mpr[row0 + tid];
        s_mpc[tid] = g_mpc[col0 + tid];
        s_negr[tid] = 0.f;
        s_negc[tid] = 0.f;
    }
    __syncthreads();

    int warp = tid >> 5, lane = tid & 31;
    int wr = warp >> 1, wc = warp & 1;
    int g = lane >> 2, t = lane & 3;
    int rbase = row0 + wr * 32;
    int cbase = col0 + wc * 64;
    const uint32_t* Vw = (const uint32_t*)g_V;  // 2 bf16 per u32, D/2=256 u32/row
    const uint32_t* Tw = (const uint32_t*)g_T;

    float acc[2][8][4];
#pragma unroll
    for (int mt = 0; mt < 2; mt++)
#pragma unroll
        for (int nt = 0; nt < 8; nt++)
#pragma unroll
            for (int v = 0; v < 4; v++) acc[mt][nt][v] = 0.f;

    for (int k0 = 0; k0 < D; k0 += 16) {
        int kw = k0 >> 1;
        uint32_t a[2][4];
#pragma unroll
        for (int mt = 0; mt < 2; mt++) {
            int r = rbase + mt * 16 + g;
            const uint32_t* p = Vw + r * (D / 2) + kw + t;
            a[mt][0] = p[0];                 // (row g,   k=t*2)
            a[mt][1] = p[8 * (D / 2)];       // (row g+8, k=t*2)
            a[mt][2] = p[4];                 // (row g,   k=t*2+8)
            a[mt][3] = p[8 * (D / 2) + 4];   // (row g+8, k=t*2+8)
        }
#pragma unroll
        for (int nt = 0; nt < 8; nt++) {
            int c = cbase + nt * 8 + g;
            const uint32_t* p = Tw + c * (D / 2) + kw + t;
            uint32_t b0 = p[0];              // (k=t*2,   col g)
            uint32_t b1 = p[4];              // (k=t*2+8, col g)
#pragma unroll
            for (int mt = 0; mt < 2; mt++) {
                asm volatile(
                    "mma.sync.aligned.m16n8k16.row.col.f32.bf16.bf16.f32 "
                    "{%0,%1,%2,%3}, {%4,%5,%6,%7}, {%8,%9}, {%0,%1,%2,%3};\n"
                    : "+f"(acc[mt][nt][0]), "+f"(acc[mt][nt][1]),
                      "+f"(acc[mt][nt][2]), "+f"(acc[mt][nt][3])
                    : "r"(a[mt][0]), "r"(a[mt][1]), "r"(a[mt][2]), "r"(a[mt][3]),
                      "r"(b0), "r"(b1));
            }
        }
    }

    // Epilogue: per-thread partials for 4 distinct rows and 16 distinct cols.
    float rloc[4] = {0.f, 0.f, 0.f, 0.f};
    float cloc[16];
#pragma unroll
    for (int q = 0; q < 16; q++) cloc[q] = 0.f;

#pragma unroll
    for (int mt = 0; mt < 2; mt++) {
#pragma unroll
        for (int nt = 0; nt < 8; nt++) {
#pragma unroll
            for (int v = 0; v < 4; v++) {
                float s = acc[mt][nt][v];
                int h = v >> 1, bb = v & 1;
                int rl = wr * 32 + mt * 16 + g + h * 8;   // block-local row
                int cl = wc * 64 + nt * 8 + t * 2 + bb;   // block-local col
                if (s_idr[rl] != s_idc[cl]) {
                    float e = __expf(s * TEMP_INV);
                    float mr = s_mpr[rl];
                    rloc[mt * 2 + h] += (s < mr && s > mr - MARGIN) ? 2.f * e : e;
                    float mc = s_mpc[cl];
                    cloc[nt * 2 + bb] += (s < mc && s > mc - MARGIN) ? 2.f * e : e;
                }
            }
        }
    }

#pragma unroll
    for (int mt = 0; mt < 2; mt++)
#pragma unroll
        for (int h = 0; h < 2; h++)
            atomicAdd(&s_negr[wr * 32 + mt * 16 + g + 8 * h], rloc[mt * 2 + h]);
#pragma unroll
    for (int nt = 0; nt < 8; nt++)
#pragma unroll
        for (int bb = 0; bb < 2; bb++)
            atomicAdd(&s_negc[wc * 64 + nt * 8 + t * 2 + bb], cloc[nt * 2 + bb]);
    __syncthreads();
    if (tid < 128) {
        atomicAdd(&g_negr[row0 + tid], s_negr[tid]);
        atomicAdd(&g_negc[col0 + tid], s_negc[tid]);
    }
}

// ---------------------------------------------------------------------------
// K4: finalize — positive-pair terms. One warp per row i; for each match j:
//   v2t += log1p(neg_row[i]/exp(sim/T)),  t2v += log1p(neg_col[j]/exp(sim/T))
// plus num_pos accumulation.
// ---------------------------------------------------------------------------
__global__ void k_final(const void* __restrict__ ids, int B) {
    const float TEMP_INV = 14.285714285714286f;
    int warp = threadIdx.x >> 5;
    int lane = threadIdx.x & 31;
    int i = blockIdx.x * 8 + warp;
    if (i >= B) return;
    long long idi = load_id(ids, i);
    int cnti = g_cnt[i];
    bool valid_i = (cnti > 0) && (cnti < B);
    float negi = g_negr[i];
    float v2t = 0.f, t2v = 0.f;
    for (int j0 = 0; j0 < B; j0 += 32) {
        int j = j0 + lane;
        bool m = (load_id(ids, j) == idi);
        unsigned mask = __ballot_sync(0xffffffffu, m);
        while (mask) {
            int jj = j0 + (__ffs(mask) - 1);
            mask &= mask - 1;
            float d = 0.f;
#pragma unroll
            for (int kk = 0; kk < D / 32; kk++) {
                int k = lane + kk * 32;
                d += __bfloat162float(g_V[i * D + k]) * __bfloat162float(g_T[jj * D + k]);
            }
#pragma unroll
            for (int o = 16; o; o >>= 1) d += __shfl_xor_sync(0xffffffffu, d, o);
            if (lane == 0) {
                float e = __expf(d * TEMP_INV);
                if (valid_i) v2t += log1pf(negi / e);
                int cntj = g_cnt[jj];
                if (cntj > 0 && cntj < B) t2v += log1pf(g_negc[jj] / e);
            }
        }
    }
    if (lane == 0) {
        atomicAdd(&g_acc[0], v2t);
        atomicAdd(&g_acc[1], t2v);
        atomicAdd(&g_acc[2], (float)cnti);
    }
}

__global__ void k_write(float* out) {
    float np = g_acc[2];
    out[0] = (np > 0.f) ? (g_acc[0] + g_acc[1]) / (2.f * fmaxf(np, 1.f)) : 0.f;
}

// ---------------------------------------------------------------------------
extern "C" void kernel_launch(void* const* d_in, const int* in_sizes, int n_in,
                              void* d_out, int out_size) {
    const float* V = (const float*)d_in[0];
    const float* T = (const float*)d_in[1];
    const void* ids = d_in[2];
    int B = in_sizes[2];
    if (B > MAXB) B = MAXB;

    k_detect<<<1, 32>>>((const unsigned int*)ids, B);
    k_init<<<(B + 255) / 256, 256>>>(B);
    dim3 gn(B, 2);
    k_norm<<<gn, 128>>>(V, T, B);
    dim3 gm((B + 7) / 8, 2);
    k_meanpos<<<gm, 256>>>(ids, B);
    dim3 gg(B / 128, B / 128);
    k_gemm<<<gg, 256>>>(ids, B);
    k_final<<<(B + 7) / 8, 256>>>(ids, B);
    k_write<<<1, 1>>>((float*)d_out);
}

// round 4
// speedup vs baseline: 2.5374x; 2.5143x over previous
#include <cuda_runtime.h>
#include <cuda_bf16.h>
#include <cstdint>
#include <math.h>

#define MAXB 4096
#define D 512
#define NSLOT 8192
#define GCAPM 64
#define EMPTYK 0x8000000000000000ull

// exp(s/T) = 2^(s * log2(e)/0.07)
#define C1 20.609929155556625f

__device__ __nv_bfloat16 g_V[MAXB * D];
__device__ __nv_bfloat16 g_T[MAXB * D];
__device__ float g_mpr[MAXB];
__device__ float g_mpc[MAXB];
__device__ float g_negr[MAXB];
__device__ float g_negc[MAXB];
__device__ unsigned long long g_hkey[NSLOT];
__device__ int   g_mcnt[NSLOT];
__device__ int   g_slot[MAXB];
__device__ int   g_memb[NSLOT * GCAPM];
__device__ float g_acc[4];
__device__ int   g_is64;

__device__ __forceinline__ long long load_id(const void* ids, int i) {
    return g_is64 ? ((const long long*)ids)[i] : (long long)((const int*)ids)[i];
}
__device__ __forceinline__ uint32_t smem_u32(const void* p) {
    uint32_t a;
    asm("{ .reg .u64 t; cvta.to.shared.u64 t, %1; cvt.u32.u64 %0, t; }" : "=r"(a) : "l"(p));
    return a;
}
__device__ __forceinline__ float ex2f(float x) {
    float y;
    asm("ex2.approx.ftz.f32 %0, %1;" : "=f"(y) : "f"(x));
    return y;
}

// ---------------------------------------------------------------------------
// K0: detect int64 vs int32 layout of match_ids.
// ---------------------------------------------------------------------------
__global__ void k_detect(const unsigned int* idw, int B) {
    int lane = threadIdx.x;
    bool nz = false;
    for (int idx = 1 + 2 * lane; idx < B; idx += 64) nz |= (idw[idx] != 0u);
    nz = __any_sync(0xffffffffu, nz);
    if (lane == 0) g_is64 = nz ? 0 : 1;
}

// K0b: zero accumulators + hash table (graph replays re-run this).
__global__ void k_init(int B) {
    int i = blockIdx.x * blockDim.x + threadIdx.x;
    if (i < B) { g_negr[i] = 0.f; g_negc[i] = 0.f; }
    if (i < NSLOT) { g_hkey[i] = EMPTYK; g_mcnt[i] = 0; }
    if (i < 4) g_acc[i] = 0.f;
}

// ---------------------------------------------------------------------------
// K1: L2-normalize rows, write bf16. blockIdx.y selects V (0) or T (1).
// ---------------------------------------------------------------------------
__global__ void k_norm(const float* __restrict__ V, const float* __restrict__ T, int B) {
    int row = blockIdx.x;
    const float* src = blockIdx.y ? T : V;
    __nv_bfloat16* dst = blockIdx.y ? g_T : g_V;
    int tid = threadIdx.x;  // 128 threads
    float x[4];
    float p = 0.f;
#pragma unroll
    for (int u = 0; u < 4; u++) {
        x[u] = src[row * D + tid + u * 128];
        p += x[u] * x[u];
    }
#pragma unroll
    for (int o = 16; o; o >>= 1) p += __shfl_xor_sync(0xffffffffu, p, o);
    __shared__ float s[4];
    if ((tid & 31) == 0) s[tid >> 5] = p;
    __syncthreads();
    float ss = s[0] + s[1] + s[2] + s[3];
    float inv = 1.f / fmaxf(sqrtf(ss), 1e-12f);
#pragma unroll
    for (int u = 0; u < 4; u++)
        dst[row * D + tid + u * 128] = __float2bfloat16(x[u] * inv);
}

// ---------------------------------------------------------------------------
// K2a: bucket ids into a hash table (linear probing).
// ---------------------------------------------------------------------------
__global__ void k_bucket(const void* __restrict__ ids, int B) {
    int i = blockIdx.x * blockDim.x + threadIdx.x;
    if (i >= B) return;
    unsigned long long key = (unsigned long long)load_id(ids, i);
    unsigned long long h64 = key * 0x9E3779B97F4A7C15ull;
    unsigned int h = (unsigned int)(h64 >> 49) & (NSLOT - 1);
    for (;;) {
        unsigned long long old = atomicCAS(&g_hkey[h], EMPTYK, key);
        if (old == EMPTYK || old == key) break;
        h = (h + 1) & (NSLOT - 1);
    }
    int pos = atomicAdd(&g_mcnt[h], 1);
    if (pos < GCAPM) g_memb[h * GCAPM + pos] = i;
    g_slot[i] = h;
}

// ---------------------------------------------------------------------------
// K2b: sparse mean_pos over group members. One warp per anchor, 2 roles.
// ---------------------------------------------------------------------------
__global__ void k_meanpos(int B) {
    int warp = threadIdx.x >> 5;
    int lane = threadIdx.x & 31;
    int a = blockIdx.x * 8 + warp;
    int role = blockIdx.y;
    if (a >= B) return;
    int slot = g_slot[a];
    int cnt = min(g_mcnt[slot], GCAPM);
    float sum = 0.f;
    for (int m = 0; m < cnt; m++) {
        int j = g_memb[slot * GCAPM + m];
        int xi = role ? j : a;  // vision index
        int yi = role ? a : j;  // text index
        float d = 0.f;
#pragma unroll
        for (int kk = 0; kk < D / 32; kk++) {
            int k = lane + kk * 32;
            d += __bfloat162float(g_V[xi * D + k]) * __bfloat162float(g_T[yi * D + k]);
        }
#pragma unroll
        for (int o = 16; o; o >>= 1) d += __shfl_xor_sync(0xffffffffu, d, o);
        sum += d;
    }
    if (lane == 0) {
        float mp = sum / (float)max(cnt, 1);
        if (role == 0) g_mpr[a] = mp;
        else           g_mpc[a] = mp;
    }
}

// ---------------------------------------------------------------------------
// K3: pipelined smem-staged mma.sync GEMM + fused hard-negative epilogue.
// 128x128 CTA tile, 8 warps (2x4), warp tile 64x32. K=512 in 8 chunks of 64.
// 3-stage cp.async pipeline, xor-swizzled 128B rows, ldmatrix.x4 loads.
// ---------------------------------------------------------------------------
#define STAGE_BYTES 32768           // A 16KB + B 16KB
#define SMEM_HDR    4096            // ids/mp/neg arrays
#define SMEM_TOTAL_GEMM (SMEM_HDR + 3 * STAGE_BYTES)  // 102400

__global__ __launch_bounds__(256, 2) void k_gemm(const void* __restrict__ ids, int B) {
    extern __shared__ char smem[];
    const uint32_t sb = smem_u32(smem);
    int tid = threadIdx.x, lane = tid & 31, wid = tid >> 5;
    int wm = wid >> 2, wn = wid & 3;
    int row0 = blockIdx.y * 128, col0 = blockIdx.x * 128;

    long long* s_idr = (long long*)(smem);            // 1024B
    long long* s_idc = (long long*)(smem + 1024);     // 1024B
    float* s_mpr  = (float*)(smem + 2048);
    float* s_mpc  = (float*)(smem + 2560);
    float* s_negr = (float*)(smem + 3072);
    float* s_negc = (float*)(smem + 3584);

    if (tid < 128) {
        s_idr[tid] = load_id(ids, row0 + tid);
        s_idc[tid] = load_id(ids, col0 + tid);
        s_mpr[tid] = g_mpr[row0 + tid];
        s_mpc[tid] = g_mpc[col0 + tid];
        s_negr[tid] = 0.f;
        s_negc[tid] = 0.f;
    }

    const char* Vb = (const char*)g_V;
    const char* Tb = (const char*)g_T;
    // loader: one chunk = A 128x128B + B 128x128B = 2048 16B units, 8/thread
    int lr = tid >> 3, lu = tid & 7;              // row (0..31 step), unit
    auto load_chunk = [&](int c, int st) {
        uint32_t sa = sb + SMEM_HDR + st * STAGE_BYTES;
#pragma unroll
        for (int t = 0; t < 4; t++) {
            int r = lr + t * 32;
            uint32_t dst = sa + (uint32_t)(r * 128 + ((lu ^ (r & 7)) << 4));
            const char* g = Vb + (size_t)(row0 + r) * 1024 + c * 128 + lu * 16;
            asm volatile("cp.async.cg.shared.global [%0], [%1], 16;" :: "r"(dst), "l"(g));
        }
#pragma unroll
        for (int t = 0; t < 4; t++) {
            int r = lr + t * 32;
            uint32_t dst = sa + 16384u + (uint32_t)(r * 128 + ((lu ^ (r & 7)) << 4));
            const char* g = Tb + (size_t)(col0 + r) * 1024 + c * 128 + lu * 16;
            asm volatile("cp.async.cg.shared.global [%0], [%1], 16;" :: "r"(dst), "l"(g));
        }
        asm volatile("cp.async.commit_group;" ::: "memory");
    };

    load_chunk(0, 0);
    load_chunk(1, 1);

    float acc[4][4][4];
#pragma unroll
    for (int mt = 0; mt < 4; mt++)
#pragma unroll
        for (int nt = 0; nt < 4; nt++)
#pragma unroll
            for (int v = 0; v < 4; v++) acc[mt][nt][v] = 0.f;

    // ldmatrix per-thread offsets (swizzle term depends only on lane)
    uint32_t rA[4], rB[2];
#pragma unroll
    for (int mt = 0; mt < 4; mt++) rA[mt] = (uint32_t)((wm * 64 + mt * 16 + (lane & 15)) * 128);
#pragma unroll
    for (int p = 0; p < 2; p++) rB[p] = 16384u + (uint32_t)((wn * 32 + p * 16 + (lane & 15)) * 128);
    uint32_t swz[4];
#pragma unroll
    for (int ks = 0; ks < 4; ks++) swz[ks] = (uint32_t)(((ks * 2 + (lane >> 4)) ^ (lane & 7)) << 4);

    for (int c = 0; c < 8; c++) {
        int st = c % 3;
        if (c < 7) asm volatile("cp.async.wait_group 1;" ::: "memory");
        else       asm volatile("cp.async.wait_group 0;" ::: "memory");
        __syncthreads();
        uint32_t sbase = sb + SMEM_HDR + st * STAGE_BYTES;
#pragma unroll
        for (int ks = 0; ks < 4; ks++) {
            uint32_t a[4][4], bm[2][4];
#pragma unroll
            for (int mt = 0; mt < 4; mt++)
                asm volatile("ldmatrix.sync.aligned.m8n8.x4.shared.b16 {%0,%1,%2,%3}, [%4];"
                             : "=r"(a[mt][0]), "=r"(a[mt][1]), "=r"(a[mt][2]), "=r"(a[mt][3])
                             : "r"(sbase + rA[mt] + swz[ks]));
#pragma unroll
            for (int p = 0; p < 2; p++)
                asm volatile("ldmatrix.sync.aligned.m8n8.x4.shared.b16 {%0,%1,%2,%3}, [%4];"
                             : "=r"(bm[p][0]), "=r"(bm[p][1]), "=r"(bm[p][2]), "=r"(bm[p][3])
                             : "r"(sbase + rB[p] + swz[ks]));
#pragma unroll
            for (int mt = 0; mt < 4; mt++)
#pragma unroll
                for (int nt = 0; nt < 4; nt++) {
                    int p = nt >> 1, hi = nt & 1;
                    asm volatile(
                        "mma.sync.aligned.m16n8k16.row.col.f32.bf16.bf16.f32 "
                        "{%0,%1,%2,%3}, {%4,%5,%6,%7}, {%8,%9}, {%0,%1,%2,%3};\n"
                        : "+f"(acc[mt][nt][0]), "+f"(acc[mt][nt][1]),
                          "+f"(acc[mt][nt][2]), "+f"(acc[mt][nt][3])
                        : "r"(a[mt][0]), "r"(a[mt][1]), "r"(a[mt][2]), "r"(a[mt][3]),
                          "r"(bm[p][hi]), "r"(bm[p][hi + 2]));
                }
        }
        if (c + 2 < 8) load_chunk(c + 2, (c + 2) % 3);
    }

    // ---- epilogue: weights + row/col partial sums
    int g = lane >> 2, t = lane & 3;
    float rloc[8], cloc[8];
#pragma unroll
    for (int q = 0; q < 8; q++) { rloc[q] = 0.f; cloc[q] = 0.f; }
#pragma unroll
    for (int mt = 0; mt < 4; mt++)
#pragma unroll
        for (int nt = 0; nt < 4; nt++)
#pragma unroll
            for (int v = 0; v < 4; v++) {
                float s = acc[mt][nt][v];
                int h = v >> 1, bb = v & 1;
                int rl = wm * 64 + mt * 16 + g + h * 8;
                int cl = wn * 32 + nt * 8 + t * 2 + bb;
                if (s_idr[rl] != s_idc[cl]) {
                    float e = ex2f(s * C1);
                    float mr = s_mpr[rl];
                    rloc[mt * 2 + h] += (s < mr && s > mr - 0.2f) ? 2.f * e : e;
                    float mc = s_mpc[cl];
                    cloc[nt * 2 + bb] += (s < mc && s > mc - 0.2f) ? 2.f * e : e;
                }
            }
#pragma unroll
    for (int mt = 0; mt < 4; mt++)
#pragma unroll
        for (int h = 0; h < 2; h++)
            atomicAdd(&s_negr[wm * 64 + mt * 16 + g + 8 * h], rloc[mt * 2 + h]);
#pragma unroll
    for (int nt = 0; nt < 4; nt++)
#pragma unroll
        for (int bb = 0; bb < 2; bb++)
            atomicAdd(&s_negc[wn * 32 + nt * 8 + t * 2 + bb], cloc[nt * 2 + bb]);
    __syncthreads();
    if (tid < 128) {
        atomicAdd(&g_negr[row0 + tid], s_negr[tid]);
        atomicAdd(&g_negc[col0 + tid], s_negc[tid]);
    }
}

// ---------------------------------------------------------------------------
// K4: finalize over positive pairs (group members). One warp per anchor row.
// ---------------------------------------------------------------------------
__global__ void k_final(int B) {
    int warp = threadIdx.x >> 5;
    int lane = threadIdx.x & 31;
    int i = blockIdx.x * 8 + warp;
    if (i >= B) return;
    int slot = g_slot[i];
    int cnt = min(g_mcnt[slot], GCAPM);
    bool valid = (cnt > 0) && (cnt < B);
    float negi = g_negr[i];
    float v2t = 0.f, t2v = 0.f;
    for (int m = 0; m < cnt; m++) {
        int j = g_memb[slot * GCAPM + m];
        float d = 0.f;
#pragma unroll
        for (int kk = 0; kk < D / 32; kk++) {
            int k = lane + kk * 32;
            d += __bfloat162float(g_V[i * D + k]) * __bfloat162float(g_T[j * D + k]);
        }
#pragma unroll
        for (int o = 16; o; o >>= 1) d += __shfl_xor_sync(0xffffffffu, d, o);
        if (lane == 0 && valid) {
            float e = ex2f(d * C1);
            v2t += log1pf(negi / e);
            t2v += log1pf(g_negc[j] / e);
        }
    }
    if (lane == 0) {
        atomicAdd(&g_acc[0], v2t);
        atomicAdd(&g_acc[1], t2v);
        atomicAdd(&g_acc[2], (float)cnt);
    }
}

__global__ void k_write(float* out) {
    float np = g_acc[2];
    out[0] = (np > 0.f) ? (g_acc[0] + g_acc[1]) / (2.f * fmaxf(np, 1.f)) : 0.f;
}

// ---------------------------------------------------------------------------
extern "C" void kernel_launch(void* const* d_in, const int* in_sizes, int n_in,
                              void* d_out, int out_size) {
    const float* V = (const float*)d_in[0];
    const float* T = (const float*)d_in[1];
    const void* ids = d_in[2];
    int B = in_sizes[2];
    if (B > MAXB) B = MAXB;

    cudaFuncSetAttribute(k_gemm, cudaFuncAttributeMaxDynamicSharedMemorySize,
                         SMEM_TOTAL_GEMM);

    k_detect<<<1, 32>>>((const unsigned int*)ids, B);
    k_init<<<(NSLOT + 255) / 256, 256>>>(B);
    dim3 gn(B, 2);
    k_norm<<<gn, 128>>>(V, T, B);
    k_bucket<<<(B + 255) / 256, 256>>>(ids, B);
    dim3 gm((B + 7) / 8, 2);
    k_meanpos<<<gm, 256>>>(B);
    dim3 gg(B / 128, B / 128);
    k_gemm<<<gg, 256, SMEM_TOTAL_GEMM>>>(ids, B);
    k_final<<<(B + 7) / 8, 256>>>(B);
    k_write<<<1, 1>>>((float*)d_out);
}

// round 5
// speedup vs baseline: 2.5583x; 1.0082x over previous
#include <cuda_runtime.h>
#include <cuda_bf16.h>
#include <cstdint>
#include <math.h>

#define MAXB 4096
#define D 512
#define NSLOT 8192
#define GCAPM 64
#define EMPTYK 0x8000000000000000ull

// exp(s/T) = 2^(s * log2(e)/0.07)
#define C1 20.609929155556625f

__device__ __nv_bfloat16 g_V[MAXB * D];
__device__ __nv_bfloat16 g_T[MAXB * D];
__device__ float g_mpr[MAXB];
__device__ float g_mpc[MAXB];
__device__ float g_negr[MAXB];
__device__ float g_negc[MAXB];
__device__ unsigned long long g_hkey[NSLOT];
__device__ int   g_mcnt[NSLOT];
__device__ int   g_slot[MAXB];
__device__ int   g_memb[NSLOT * GCAPM];
__device__ float g_acc[4];
__device__ int   g_is64;

__device__ __forceinline__ long long load_id(const void* ids, int i) {
    return g_is64 ? ((const long long*)ids)[i] : (long long)((const int*)ids)[i];
}
__device__ __forceinline__ uint32_t smem_u32(const void* p) {
    uint32_t a;
    asm("{ .reg .u64 t; cvta.to.shared.u64 t, %1; cvt.u32.u64 %0, t; }" : "=r"(a) : "l"(p));
    return a;
}
__device__ __forceinline__ float ex2f(float x) {
    float y;
    asm("ex2.approx.ftz.f32 %0, %1;" : "=f"(y) : "f"(x));
    return y;
}

// ---------------------------------------------------------------------------
// K0: detect int64 vs int32 layout of match_ids.
// ---------------------------------------------------------------------------
__global__ void k_detect(const unsigned int* idw, int B) {
    int lane = threadIdx.x;
    bool nz = false;
    for (int idx = 1 + 2 * lane; idx < B; idx += 64) nz |= (idw[idx] != 0u);
    nz = __any_sync(0xffffffffu, nz);
    if (lane == 0) g_is64 = nz ? 0 : 1;
}

// K0b: zero accumulators + hash table (graph replays re-run this).
__global__ void k_init(int B) {
    int i = blockIdx.x * blockDim.x + threadIdx.x;
    if (i < B) { g_negr[i] = 0.f; g_negc[i] = 0.f; }
    if (i < NSLOT) { g_hkey[i] = EMPTYK; g_mcnt[i] = 0; }
    if (i < 4) g_acc[i] = 0.f;
}

// ---------------------------------------------------------------------------
// K1: L2-normalize rows, write bf16. blockIdx.y selects V (0) or T (1).
// ---------------------------------------------------------------------------
__global__ void k_norm(const float* __restrict__ V, const float* __restrict__ T, int B) {
    int row = blockIdx.x;
    const float* src = blockIdx.y ? T : V;
    __nv_bfloat16* dst = blockIdx.y ? g_T : g_V;
    int tid = threadIdx.x;  // 128 threads
    float x[4];
    float p = 0.f;
#pragma unroll
    for (int u = 0; u < 4; u++) {
        x[u] = src[row * D + tid + u * 128];
        p += x[u] * x[u];
    }
#pragma unroll
    for (int o = 16; o; o >>= 1) p += __shfl_xor_sync(0xffffffffu, p, o);
    __shared__ float s[4];
    if ((tid & 31) == 0) s[tid >> 5] = p;
    __syncthreads();
    float ss = s[0] + s[1] + s[2] + s[3];
    float inv = 1.f / fmaxf(sqrtf(ss), 1e-12f);
#pragma unroll
    for (int u = 0; u < 4; u++)
        dst[row * D + tid + u * 128] = __float2bfloat16(x[u] * inv);
}

// ---------------------------------------------------------------------------
// K2a: bucket ids into a hash table (linear probing).
// ---------------------------------------------------------------------------
__global__ void k_bucket(const void* __restrict__ ids, int B) {
    int i = blockIdx.x * blockDim.x + threadIdx.x;
    if (i >= B) return;
    unsigned long long key = (unsigned long long)load_id(ids, i);
    unsigned long long h64 = key * 0x9E3779B97F4A7C15ull;
    unsigned int h = (unsigned int)(h64 >> 49) & (NSLOT - 1);
    for (;;) {
        unsigned long long old = atomicCAS(&g_hkey[h], EMPTYK, key);
        if (old == EMPTYK || old == key) break;
        h = (h + 1) & (NSLOT - 1);
    }
    int pos = atomicAdd(&g_mcnt[h], 1);
    if (pos < GCAPM) g_memb[h * GCAPM + pos] = i;
    g_slot[i] = h;
}

// ---------------------------------------------------------------------------
// K2b: sparse mean_pos over group members. One warp per anchor, 2 roles.
// ---------------------------------------------------------------------------
__global__ void k_meanpos(int B) {
    int warp = threadIdx.x >> 5;
    int lane = threadIdx.x & 31;
    int a = blockIdx.x * 8 + warp;
    int role = blockIdx.y;
    if (a >= B) return;
    int slot = g_slot[a];
    int cnt = min(g_mcnt[slot], GCAPM);
    float sum = 0.f;
    for (int m = 0; m < cnt; m++) {
        int j = g_memb[slot * GCAPM + m];
        int xi = role ? j : a;  // vision index
        int yi = role ? a : j;  // text index
        float d = 0.f;
#pragma unroll
        for (int kk = 0; kk < D / 32; kk++) {
            int k = lane + kk * 32;
            d += __bfloat162float(g_V[xi * D + k]) * __bfloat162float(g_T[yi * D + k]);
        }
#pragma unroll
        for (int o = 16; o; o >>= 1) d += __shfl_xor_sync(0xffffffffu, d, o);
        sum += d;
    }
    if (lane == 0) {
        float mp = sum / (float)max(cnt, 1);
        if (role == 0) g_mpr[a] = mp;
        else           g_mpc[a] = mp;
    }
}

// ---------------------------------------------------------------------------
// K3: pipelined smem-staged mma.sync GEMM + fused hard-negative epilogue.
// 128x128 CTA tile, 8 warps (2x4), warp tile 64x32. K=512 in 8 chunks of 64.
// 3-stage cp.async pipeline, xor-swizzled 128B rows, ldmatrix.x4 loads.
// ---------------------------------------------------------------------------
#define STAGE_BYTES 32768           // A 16KB + B 16KB
#define SMEM_HDR    4096            // ids/mp/neg arrays
#define SMEM_TOTAL_GEMM (SMEM_HDR + 3 * STAGE_BYTES)  // 102400

__global__ __launch_bounds__(256, 2) void k_gemm(const void* __restrict__ ids, int B) {
    extern __shared__ char smem[];
    const uint32_t sb = smem_u32(smem);
    int tid = threadIdx.x, lane = tid & 31, wid = tid >> 5;
    int wm = wid >> 2, wn = wid & 3;
    int row0 = blockIdx.y * 128, col0 = blockIdx.x * 128;

    long long* s_idr = (long long*)(smem);            // 1024B
    long long* s_idc = (long long*)(smem + 1024);     // 1024B
    float* s_mpr  = (float*)(smem + 2048);
    float* s_mpc  = (float*)(smem + 2560);
    float* s_negr = (float*)(smem + 3072);
    float* s_negc = (float*)(smem + 3584);

    if (tid < 128) {
        s_idr[tid] = load_id(ids, row0 + tid);
        s_idc[tid] = load_id(ids, col0 + tid);
        s_mpr[tid] = g_mpr[row0 + tid];
        s_mpc[tid] = g_mpc[col0 + tid];
        s_negr[tid] = 0.f;
        s_negc[tid] = 0.f;
    }

    const char* Vb = (const char*)g_V;
    const char* Tb = (const char*)g_T;
    // loader: one chunk = A 128x128B + B 128x128B = 2048 16B units, 8/thread
    int lr = tid >> 3, lu = tid & 7;              // row (0..31 step), unit
    auto load_chunk = [&](int c, int st) {
        uint32_t sa = sb + SMEM_HDR + st * STAGE_BYTES;
#pragma unroll
        for (int t = 0; t < 4; t++) {
            int r = lr + t * 32;
            uint32_t dst = sa + (uint32_t)(r * 128 + ((lu ^ (r & 7)) << 4));
            const char* g = Vb + (size_t)(row0 + r) * 1024 + c * 128 + lu * 16;
            asm volatile("cp.async.cg.shared.global [%0], [%1], 16;" :: "r"(dst), "l"(g));
        }
#pragma unroll
        for (int t = 0; t < 4; t++) {
            int r = lr + t * 32;
            uint32_t dst = sa + 16384u + (uint32_t)(r * 128 + ((lu ^ (r & 7)) << 4));
            const char* g = Tb + (size_t)(col0 + r) * 1024 + c * 128 + lu * 16;
            asm volatile("cp.async.cg.shared.global [%0], [%1], 16;" :: "r"(dst), "l"(g));
        }
        asm volatile("cp.async.commit_group;" ::: "memory");
    };

    load_chunk(0, 0);
    load_chunk(1, 1);

    float acc[4][4][4];
#pragma unroll
    for (int mt = 0; mt < 4; mt++)
#pragma unroll
        for (int nt = 0; nt < 4; nt++)
#pragma unroll
            for (int v = 0; v < 4; v++) acc[mt][nt][v] = 0.f;

    // ldmatrix per-thread offsets (swizzle term depends only on lane)
    uint32_t rA[4], rB[2];
#pragma unroll
    for (int mt = 0; mt < 4; mt++) rA[mt] = (uint32_t)((wm * 64 + mt * 16 + (lane & 15)) * 128);
#pragma unroll
    for (int p = 0; p < 2; p++) rB[p] = 16384u + (uint32_t)((wn * 32 + p * 16 + (lane & 15)) * 128);
    uint32_t swz[4];
#pragma unroll
    for (int ks = 0; ks < 4; ks++) swz[ks] = (uint32_t)(((ks * 2 + (lane >> 4)) ^ (lane & 7)) << 4);

    for (int c = 0; c < 8; c++) {
        int st = c % 3;
        if (c < 7) asm volatile("cp.async.wait_group 1;" ::: "memory");
        else       asm volatile("cp.async.wait_group 0;" ::: "memory");
        __syncthreads();
        uint32_t sbase = sb + SMEM_HDR + st * STAGE_BYTES;
#pragma unroll
        for (int ks = 0; ks < 4; ks++) {
            uint32_t a[4][4], bm[2][4];
#pragma unroll
            for (int mt = 0; mt < 4; mt++)
                asm volatile("ldmatrix.sync.aligned.m8n8.x4.shared.b16 {%0,%1,%2,%3}, [%4];"
                             : "=r"(a[mt][0]), "=r"(a[mt][1]), "=r"(a[mt][2]), "=r"(a[mt][3])
                             : "r"(sbase + rA[mt] + swz[ks]));
#pragma unroll
            for (int p = 0; p < 2; p++)
                asm volatile("ldmatrix.sync.aligned.m8n8.x4.shared.b16 {%0,%1,%2,%3}, [%4];"
                             : "=r"(bm[p][0]), "=r"(bm[p][1]), "=r"(bm[p][2]), "=r"(bm[p][3])
                             : "r"(sbase + rB[p] + swz[ks]));
#pragma unroll
            for (int mt = 0; mt < 4; mt++)
#pragma unroll
                for (int nt = 0; nt < 4; nt++) {
                    int p = nt >> 1, hi = nt & 1;
                    asm volatile(
                        "mma.sync.aligned.m16n8k16.row.col.f32.bf16.bf16.f32 "
                        "{%0,%1,%2,%3}, {%4,%5,%6,%7}, {%8,%9}, {%0,%1,%2,%3};\n"
                        : "+f"(acc[mt][nt][0]), "+f"(acc[mt][nt][1]),
                          "+f"(acc[mt][nt][2]), "+f"(acc[mt][nt][3])
                        : "r"(a[mt][0]), "r"(a[mt][1]), "r"(a[mt][2]), "r"(a[mt][3]),
                          "r"(bm[p][hi]), "r"(bm[p][hi + 2]));
                }
        }
        if (c + 2 < 8) load_chunk(c + 2, (c + 2) % 3);
    }

    // ---- epilogue: weights + row/col partial sums
    int g = lane >> 2, t = lane & 3;
    float rloc[8], cloc[8];
#pragma unroll
    for (int q = 0; q < 8; q++) { rloc[q] = 0.f; cloc[q] = 0.f; }
#pragma unroll
    for (int mt = 0; mt < 4; mt++)
#pragma unroll
        for (int nt = 0; nt < 4; nt++)
#pragma unroll
            for (int v = 0; v < 4; v++) {
                float s = acc[mt][nt][v];
                int h = v >> 1, bb = v & 1;
                int rl = wm * 64 + mt * 16 + g + h * 8;
                int cl = wn * 32 + nt * 8 + t * 2 + bb;
                if (s_idr[rl] != s_idc[cl]) {
                    float e = ex2f(s * C1);
                    float mr = s_mpr[rl];
                    rloc[mt * 2 + h] += (s < mr && s > mr - 0.2f) ? 2.f * e : e;
                    float mc = s_mpc[cl];
                    cloc[nt * 2 + bb] += (s < mc && s > mc - 0.2f) ? 2.f * e : e;
                }
            }
#pragma unroll
    for (int mt = 0; mt < 4; mt++)
#pragma unroll
        for (int h = 0; h < 2; h++)
            atomicAdd(&s_negr[wm * 64 + mt * 16 + g + 8 * h], rloc[mt * 2 + h]);
#pragma unroll
    for (int nt = 0; nt < 4; nt++)
#pragma unroll
        for (int bb = 0; bb < 2; bb++)
            atomicAdd(&s_negc[wn * 32 + nt * 8 + t * 2 + bb], cloc[nt * 2 + bb]);
    __syncthreads();
    if (tid < 128) {
        atomicAdd(&g_negr[row0 + tid], s_negr[tid]);
        atomicAdd(&g_negc[col0 + tid], s_negc[tid]);
    }
}

// ---------------------------------------------------------------------------
// K4: finalize over positive pairs (group members). One warp per anchor row.
// ---------------------------------------------------------------------------
__global__ void k_final(int B) {
    int warp = threadIdx.x >> 5;
    int lane = threadIdx.x & 31;
    int i = blockIdx.x * 8 + warp;
    if (i >= B) return;
    int slot = g_slot[i];
    int cnt = min(g_mcnt[slot], GCAPM);
    bool valid = (cnt > 0) && (cnt < B);
    float negi = g_negr[i];
    float v2t = 0.f, t2v = 0.f;
    for (int m = 0; m < cnt; m++) {
        int j = g_memb[slot * GCAPM + m];
        float d = 0.f;
#pragma unroll
        for (int kk = 0; kk < D / 32; kk++) {
            int k = lane + kk * 32;
            d += __bfloat162float(g_V[i * D + k]) * __bfloat162float(g_T[j * D + k]);
        }
#pragma unroll
        for (int o = 16; o; o >>= 1) d += __shfl_xor_sync(0xffffffffu, d, o);
        if (lane == 0 && valid) {
            float e = ex2f(d * C1);
            v2t += log1pf(negi / e);
            t2v += log1pf(g_negc[j] / e);
        }
    }
    if (lane == 0) {
        atomicAdd(&g_acc[0], v2t);
        atomicAdd(&g_acc[1], t2v);
        atomicAdd(&g_acc[2], (float)cnt);
    }
}

__global__ void k_write(float* out) {
    float np = g_acc[2];
    out[0] = (np > 0.f) ? (g_acc[0] + g_acc[1]) / (2.f * fmaxf(np, 1.f)) : 0.f;
}

// ---------------------------------------------------------------------------
extern "C" void kernel_launch(void* const* d_in, const int* in_sizes, int n_in,
                              void* d_out, int out_size) {
    const float* V = (const float*)d_in[0];
    const float* T = (const float*)d_in[1];
    const void* ids = d_in[2];
    int B = in_sizes[2];
    if (B > MAXB) B = MAXB;

    cudaFuncSetAttribute(k_gemm, cudaFuncAttributeMaxDynamicSharedMemorySize,
                         SMEM_TOTAL_GEMM);

    k_detect<<<1, 32>>>((const unsigned int*)ids, B);
    k_init<<<(NSLOT + 255) / 256, 256>>>(B);
    dim3 gn(B, 2);
    k_norm<<<gn, 128>>>(V, T, B);
    k_bucket<<<(B + 255) / 256, 256>>>(ids, B);
    dim3 gm((B + 7) / 8, 2);
    k_meanpos<<<gm, 256>>>(B);
    dim3 gg(B / 128, B / 128);
    k_gemm<<<gg, 256, SMEM_TOTAL_GEMM>>>(ids, B);
    k_final<<<(B + 7) / 8, 256>>>(B);
    k_write<<<1, 1>>>((float*)d_out);
}

// round 6
// speedup vs baseline: 2.5771x; 1.0073x over previous
#include <cuda_runtime.h>
#include <cuda_bf16.h>
#include <cstdint>
#include <math.h>

#define MAXB 4096
#define D 512
#define NSLOT 8192
#define GCAPM 64
#define EMPTYK 0x8000000000000000ull

// exp(s/T) = 2^(s * log2(e)/0.07)
#define C1 20.609929155556625f

__device__ __nv_bfloat16 g_V[MAXB * D];
__device__ __nv_bfloat16 g_T[MAXB * D];
__device__ float g_mpr[MAXB];
__device__ float g_mpc[MAXB];
__device__ float g_negr[MAXB];
__device__ float g_negc[MAXB];
__device__ unsigned long long g_hkey[NSLOT];
__device__ int   g_mcnt[NSLOT];
__device__ int   g_slot[MAXB];
__device__ int   g_memb[NSLOT * GCAPM];
__device__ float g_acc[4];
__device__ int   g_is64;

__device__ __forceinline__ long long load_id(const void* ids, int i) {
    return g_is64 ? ((const long long*)ids)[i] : (long long)((const int*)ids)[i];
}
__device__ __forceinline__ uint32_t smem_u32(const void* p) {
    uint32_t a;
    asm("{ .reg .u64 t; cvta.to.shared.u64 t, %1; cvt.u32.u64 %0, t; }" : "=r"(a) : "l"(p));
    return a;
}
__device__ __forceinline__ float ex2f(float x) {
    float y;
    asm("ex2.approx.ftz.f32 %0, %1;" : "=f"(y) : "f"(x));
    return y;
}

// ---------------------------------------------------------------------------
// K0: detect int64 vs int32 layout of match_ids.
// ---------------------------------------------------------------------------
__global__ void k_detect(const unsigned int* idw, int B) {
    int lane = threadIdx.x;
    bool nz = false;
    for (int idx = 1 + 2 * lane; idx < B; idx += 64) nz |= (idw[idx] != 0u);
    nz = __any_sync(0xffffffffu, nz);
    if (lane == 0) g_is64 = nz ? 0 : 1;
}

// K0b: zero accumulators + hash table (graph replays re-run this).
__global__ void k_init(int B) {
    int i = blockIdx.x * blockDim.x + threadIdx.x;
    if (i < B) { g_negr[i] = 0.f; g_negc[i] = 0.f; }
    if (i < NSLOT) { g_hkey[i] = EMPTYK; g_mcnt[i] = 0; }
    if (i < 4) g_acc[i] = 0.f;
}

// ---------------------------------------------------------------------------
// K1: L2-normalize rows, write bf16. blockIdx.y selects V (0) or T (1).
// ---------------------------------------------------------------------------
__global__ void k_norm(const float* __restrict__ V, const float* __restrict__ T, int B) {
    int row = blockIdx.x;
    const float* src = blockIdx.y ? T : V;
    __nv_bfloat16* dst = blockIdx.y ? g_T : g_V;
    int tid = threadIdx.x;  // 128 threads
    float x[4];
    float p = 0.f;
#pragma unroll
    for (int u = 0; u < 4; u++) {
        x[u] = src[row * D + tid + u * 128];
        p += x[u] * x[u];
    }
#pragma unroll
    for (int o = 16; o; o >>= 1) p += __shfl_xor_sync(0xffffffffu, p, o);
    __shared__ float s[4];
    if ((tid & 31) == 0) s[tid >> 5] = p;
    __syncthreads();
    float ss = s[0] + s[1] + s[2] + s[3];
    float inv = 1.f / fmaxf(sqrtf(ss), 1e-12f);
#pragma unroll
    for (int u = 0; u < 4; u++)
        dst[row * D + tid + u * 128] = __float2bfloat16(x[u] * inv);
}

// ---------------------------------------------------------------------------
// K2a: bucket ids into a hash table (linear probing).
// ---------------------------------------------------------------------------
__global__ void k_bucket(const void* __restrict__ ids, int B) {
    int i = blockIdx.x * blockDim.x + threadIdx.x;
    if (i >= B) return;
    unsigned long long key = (unsigned long long)load_id(ids, i);
    unsigned long long h64 = key * 0x9E3779B97F4A7C15ull;
    unsigned int h = (unsigned int)(h64 >> 49) & (NSLOT - 1);
    for (;;) {
        unsigned long long old = atomicCAS(&g_hkey[h], EMPTYK, key);
        if (old == EMPTYK || old == key) break;
        h = (h + 1) & (NSLOT - 1);
    }
    int pos = atomicAdd(&g_mcnt[h], 1);
    if (pos < GCAPM) g_memb[h * GCAPM + pos] = i;
    g_slot[i] = h;
}

// ---------------------------------------------------------------------------
// K2b: sparse mean_pos over group members. One warp per anchor, 2 roles.
// ---------------------------------------------------------------------------
__global__ void k_meanpos(int B) {
    int warp = threadIdx.x >> 5;
    int lane = threadIdx.x & 31;
    int a = blockIdx.x * 8 + warp;
    int role = blockIdx.y;
    if (a >= B) return;
    int slot = g_slot[a];
    int cnt = min(g_mcnt[slot], GCAPM);
    float sum = 0.f;
    for (int m = 0; m < cnt; m++) {
        int j = g_memb[slot * GCAPM + m];
        int xi = role ? j : a;  // vision index
        int yi = role ? a : j;  // text index
        float d = 0.f;
#pragma unroll
        for (int kk = 0; kk < D / 32; kk++) {
            int k = lane + kk * 32;
            d += __bfloat162float(g_V[xi * D + k]) * __bfloat162float(g_T[yi * D + k]);
        }
#pragma unroll
        for (int o = 16; o; o >>= 1) d += __shfl_xor_sync(0xffffffffu, d, o);
        sum += d;
    }
    if (lane == 0) {
        float mp = sum / (float)max(cnt, 1);
        if (role == 0) g_mpr[a] = mp;
        else           g_mpc[a] = mp;
    }
}

// ---------------------------------------------------------------------------
// K3: pipelined smem-staged mma.sync GEMM + fused hard-negative epilogue.
// 128x128 CTA tile, 8 warps (2x4), warp tile 64x32. K=512 in 8 chunks of 64.
// 3-stage cp.async pipeline, xor-swizzled 128B rows, ldmatrix.x4 loads.
// ---------------------------------------------------------------------------
#define STAGE_BYTES 32768           // A 16KB + B 16KB
#define SMEM_HDR    4096            // ids/mp/neg arrays
#define SMEM_TOTAL_GEMM (SMEM_HDR + 3 * STAGE_BYTES)  // 102400

__global__ __launch_bounds__(256, 2) void k_gemm(const void* __restrict__ ids, int B) {
    extern __shared__ char smem[];
    const uint32_t sb = smem_u32(smem);
    int tid = threadIdx.x, lane = tid & 31, wid = tid >> 5;
    int wm = wid >> 2, wn = wid & 3;
    int row0 = blockIdx.y * 128, col0 = blockIdx.x * 128;

    long long* s_idr = (long long*)(smem);            // 1024B
    long long* s_idc = (long long*)(smem + 1024);     // 1024B
    float* s_mpr  = (float*)(smem + 2048);
    float* s_mpc  = (float*)(smem + 2560);
    float* s_negr = (float*)(smem + 3072);
    float* s_negc = (float*)(smem + 3584);

    if (tid < 128) {
        s_idr[tid] = load_id(ids, row0 + tid);
        s_idc[tid] = load_id(ids, col0 + tid);
        s_mpr[tid] = g_mpr[row0 + tid];
        s_mpc[tid] = g_mpc[col0 + tid];
        s_negr[tid] = 0.f;
        s_negc[tid] = 0.f;
    }

    const char* Vb = (const char*)g_V;
    const char* Tb = (const char*)g_T;
    // loader: one chunk = A 128x128B + B 128x128B = 2048 16B units, 8/thread
    int lr = tid >> 3, lu = tid & 7;              // row (0..31 step), unit
    auto load_chunk = [&](int c, int st) {
        uint32_t sa = sb + SMEM_HDR + st * STAGE_BYTES;
#pragma unroll
        for (int t = 0; t < 4; t++) {
            int r = lr + t * 32;
            uint32_t dst = sa + (uint32_t)(r * 128 + ((lu ^ (r & 7)) << 4));
            const char* g = Vb + (size_t)(row0 + r) * 1024 + c * 128 + lu * 16;
            asm volatile("cp.async.cg.shared.global [%0], [%1], 16;" :: "r"(dst), "l"(g));
        }
#pragma unroll
        for (int t = 0; t < 4; t++) {
            int r = lr + t * 32;
            uint32_t dst = sa + 16384u + (uint32_t)(r * 128 + ((lu ^ (r & 7)) << 4));
            const char* g = Tb + (size_t)(col0 + r) * 1024 + c * 128 + lu * 16;
            asm volatile("cp.async.cg.shared.global [%0], [%1], 16;" :: "r"(dst), "l"(g));
        }
        asm volatile("cp.async.commit_group;" ::: "memory");
    };

    load_chunk(0, 0);
    load_chunk(1, 1);

    float acc[4][4][4];
#pragma unroll
    for (int mt = 0; mt < 4; mt++)
#pragma unroll
        for (int nt = 0; nt < 4; nt++)
#pragma unroll
            for (int v = 0; v < 4; v++) acc[mt][nt][v] = 0.f;

    // ldmatrix per-thread offsets (swizzle term depends only on lane)
    uint32_t rA[4], rB[2];
#pragma unroll
    for (int mt = 0; mt < 4; mt++) rA[mt] = (uint32_t)((wm * 64 + mt * 16 + (lane & 15)) * 128);
#pragma unroll
    for (int p = 0; p < 2; p++) rB[p] = 16384u + (uint32_t)((wn * 32 + p * 16 + (lane & 15)) * 128);
    uint32_t swz[4];
#pragma unroll
    for (int ks = 0; ks < 4; ks++) swz[ks] = (uint32_t)(((ks * 2 + (lane >> 4)) ^ (lane & 7)) << 4);

    for (int c = 0; c < 8; c++) {
        int st = c % 3;
        if (c < 7) asm volatile("cp.async.wait_group 1;" ::: "memory");
        else       asm volatile("cp.async.wait_group 0;" ::: "memory");
        __syncthreads();
        uint32_t sbase = sb + SMEM_HDR + st * STAGE_BYTES;
#pragma unroll
        for (int ks = 0; ks < 4; ks++) {
            uint32_t a[4][4], bm[2][4];
#pragma unroll
            for (int mt = 0; mt < 4; mt++)
                asm volatile("ldmatrix.sync.aligned.m8n8.x4.shared.b16 {%0,%1,%2,%3}, [%4];"
                             : "=r"(a[mt][0]), "=r"(a[mt][1]), "=r"(a[mt][2]), "=r"(a[mt][3])
                             : "r"(sbase + rA[mt] + swz[ks]));
#pragma unroll
            for (int p = 0; p < 2; p++)
                asm volatile("ldmatrix.sync.aligned.m8n8.x4.shared.b16 {%0,%1,%2,%3}, [%4];"
                             : "=r"(bm[p][0]), "=r"(bm[p][1]), "=r"(bm[p][2]), "=r"(bm[p][3])
                             : "r"(sbase + rB[p] + swz[ks]));
#pragma unroll
            for (int mt = 0; mt < 4; mt++)
#pragma unroll
                for (int nt = 0; nt < 4; nt++) {
                    int p = nt >> 1, hi = nt & 1;
                    asm volatile(
                        "mma.sync.aligned.m16n8k16.row.col.f32.bf16.bf16.f32 "
                        "{%0,%1,%2,%3}, {%4,%5,%6,%7}, {%8,%9}, {%0,%1,%2,%3};\n"
                        : "+f"(acc[mt][nt][0]), "+f"(acc[mt][nt][1]),
                          "+f"(acc[mt][nt][2]), "+f"(acc[mt][nt][3])
                        : "r"(a[mt][0]), "r"(a[mt][1]), "r"(a[mt][2]), "r"(a[mt][3]),
                          "r"(bm[p][hi]), "r"(bm[p][hi + 2]));
                }
        }
        if (c + 2 < 8) load_chunk(c + 2, (c + 2) % 3);
    }

    // ---- epilogue: weights + row/col partial sums
    int g = lane >> 2, t = lane & 3;
    float rloc[8], cloc[8];
#pragma unroll
    for (int q = 0; q < 8; q++) { rloc[q] = 0.f; cloc[q] = 0.f; }
#pragma unroll
    for (int mt = 0; mt < 4; mt++)
#pragma unroll
        for (int nt = 0; nt < 4; nt++)
#pragma unroll
            for (int v = 0; v < 4; v++) {
                float s = acc[mt][nt][v];
                int h = v >> 1, bb = v & 1;
                int rl = wm * 64 + mt * 16 + g + h * 8;
                int cl = wn * 32 + nt * 8 + t * 2 + bb;
                if (s_idr[rl] != s_idc[cl]) {
                    float e = ex2f(s * C1);
                    float mr = s_mpr[rl];
                    rloc[mt * 2 + h] += (s < mr && s > mr - 0.2f) ? 2.f * e : e;
                    float mc = s_mpc[cl];
                    cloc[nt * 2 + bb] += (s < mc && s > mc - 0.2f) ? 2.f * e : e;
                }
            }
#pragma unroll
    for (int mt = 0; mt < 4; mt++)
#pragma unroll
        for (int h = 0; h < 2; h++)
            atomicAdd(&s_negr[wm * 64 + mt * 16 + g + 8 * h], rloc[mt * 2 + h]);
#pragma unroll
    for (int nt = 0; nt < 4; nt++)
#pragma unroll
        for (int bb = 0; bb < 2; bb++)
            atomicAdd(&s_negc[wn * 32 + nt * 8 + t * 2 + bb], cloc[nt * 2 + bb]);
    __syncthreads();
    if (tid < 128) {
        atomicAdd(&g_negr[row0 + tid], s_negr[tid]);
        atomicAdd(&g_negc[col0 + tid], s_negc[tid]);
    }
}

// ---------------------------------------------------------------------------
// K4: finalize over positive pairs (group members). One warp per anchor row.
// ---------------------------------------------------------------------------
__global__ void k_final(int B) {
    int warp = threadIdx.x >> 5;
    int lane = threadIdx.x & 31;
    int i = blockIdx.x * 8 + warp;
    if (i >= B) return;
    int slot = g_slot[i];
    int cnt = min(g_mcnt[slot], GCAPM);
    bool valid = (cnt > 0) && (cnt < B);
    float negi = g_negr[i];
    float v2t = 0.f, t2v = 0.f;
    for (int m = 0; m < cnt; m++) {
        int j = g_memb[slot * GCAPM + m];
        float d = 0.f;
#pragma unroll
        for (int kk = 0; kk < D / 32; kk++) {
            int k = lane + kk * 32;
            d += __bfloat162float(g_V[i * D + k]) * __bfloat162float(g_T[j * D + k]);
        }
#pragma unroll
        for (int o = 16; o; o >>= 1) d += __shfl_xor_sync(0xffffffffu, d, o);
        if (lane == 0 && valid) {
            float e = ex2f(d * C1);
            v2t += log1pf(negi / e);
            t2v += log1pf(g_negc[j] / e);
        }
    }
    if (lane == 0) {
        atomicAdd(&g_acc[0], v2t);
        atomicAdd(&g_acc[1], t2v);
        atomicAdd(&g_acc[2], (float)cnt);
    }
}

__global__ void k_write(float* out) {
    float np = g_acc[2];
    out[0] = (np > 0.f) ? (g_acc[0] + g_acc[1]) / (2.f * fmaxf(np, 1.f)) : 0.f;
}

// ---------------------------------------------------------------------------
extern "C" void kernel_launch(void* const* d_in, const int* in_sizes, int n_in,
                              void* d_out, int out_size) {
    const float* V = (const float*)d_in[0];
    const float* T = (const float*)d_in[1];
    const void* ids = d_in[2];
    int B = in_sizes[2];
    if (B > MAXB) B = MAXB;

    cudaFuncSetAttribute(k_gemm, cudaFuncAttributeMaxDynamicSharedMemorySize,
                         SMEM_TOTAL_GEMM);

    k_detect<<<1, 32>>>((const unsigned int*)ids, B);
    k_init<<<(NSLOT + 255) / 256, 256>>>(B);
    dim3 gn(B, 2);
    k_norm<<<gn, 128>>>(V, T, B);
    k_bucket<<<(B + 255) / 256, 256>>>(ids, B);
    dim3 gm((B + 7) / 8, 2);
    k_meanpos<<<gm, 256>>>(B);
    dim3 gg(B / 128, B / 128);
    k_gemm<<<gg, 256, SMEM_TOTAL_GEMM>>>(ids, B);
    k_final<<<(B + 7) / 8, 256>>>(B);
    k_write<<<1, 1>>>((float*)d_out);
}